// round 13
// baseline (speedup 1.0000x reference)
#include <cuda_runtime.h>
#include <cuda_fp16.h>

#define NN   50000
#define EE   1600000
#define DD   128
#define KK   16
#define ALPHA_F 0.05f
#define CW_F    (0.95f / 16.0f)
#define NPAD 50048
#define NBLK 49            // ceil(NN/1024)
#define ROW32 (NPAD * 32)  // uint2 groups per buffer

// -------------------- scratch (static device globals; no allocs) ------------
// 17 fp16 y-buffers: y_k = dinv .* x_k ; buffer 0 = y_0, k = A-hat hops
__device__ uint2 g_xbuf[(KK + 1) * ROW32];   // ~217 MB, pad rows stay zero
__device__ int   g_deg[NN];                  // edge in-degree (no self loop); 0 at entry
__device__ float g_dinv[NN];
__device__ float g_csc[NN];                  // CW_F * sqrt(deg+1) = CW_F / dinv
__device__ int   g_rowptr[NN + 1];
__device__ int   g_cursor[NN];
__device__ int   g_col[EE];                  // source node per CSR slot
__device__ int   g_bsum[NBLK];

// -------------------- L1: degree count (deg starts at 0) --------------------
__global__ void count_deg_kernel(const int* __restrict__ dst) {
    for (int e = blockIdx.x * blockDim.x + threadIdx.x; e < EE;
         e += gridDim.x * blockDim.x) {
        atomicAdd(&g_deg[dst[e]], 1);
    }
}

// -------------------- L2: cursor + dinv + csc + fp16 y0 ---------------------
__global__ void prep_kernel(const float* __restrict__ x0) {
    int idx = blockIdx.x * blockDim.x + threadIdx.x;
    const int total = NN * 32;
    if (idx < total) {
        int node = idx >> 5;
        float dv = rsqrtf((float)(g_deg[node] + 1));
        float4 v = ((const float4*)x0)[idx];
        __half2 p01 = __floats2half2_rn(dv * v.x, dv * v.y);
        __half2 p23 = __floats2half2_rn(dv * v.z, dv * v.w);
        uint2 o;
        o.x = *(unsigned int*)&p01;
        o.y = *(unsigned int*)&p23;
        g_xbuf[idx] = o;
    }
    if (idx < NN) {
        float dp1 = (float)(g_deg[idx] + 1);
        g_dinv[idx] = rsqrtf(dp1);
        g_csc[idx]  = CW_F * sqrtf(dp1);
        g_cursor[idx] = 0;
    }
}

// -------------------- L3: per-block sums of deg -----------------------------
__global__ void scan1_kernel() {
    __shared__ int ws[32];
    int tid = threadIdx.x;
    int i = blockIdx.x * 1024 + tid;
    int v = (i < NN) ? g_deg[i] : 0;
    #pragma unroll
    for (int d = 16; d > 0; d >>= 1) v += __shfl_down_sync(0xffffffffu, v, d);
    if ((tid & 31) == 0) ws[tid >> 5] = v;
    __syncthreads();
    if (tid < 32) {
        int s = ws[tid];
        #pragma unroll
        for (int d = 16; d > 0; d >>= 1) s += __shfl_down_sync(0xffffffffu, s, d);
        if (tid == 0) g_bsum[blockIdx.x] = s;
    }
}

// -------------------- L4: block scan + inline prefix-of-bsums ---------------
__device__ __forceinline__ int block_scan_inc(int v, int tid) {
    __shared__ int ws[32];
    const int lane = tid & 31, wid = tid >> 5;
    int x = v;
    #pragma unroll
    for (int d = 1; d < 32; d <<= 1) {
        int y = __shfl_up_sync(0xffffffffu, x, d);
        if (lane >= d) x += y;
    }
    if (lane == 31) ws[wid] = x;
    __syncthreads();
    if (wid == 0) {
        int s = ws[lane];
        int t = s;
        #pragma unroll
        for (int d = 1; d < 32; d <<= 1) {
            int y = __shfl_up_sync(0xffffffffu, t, d);
            if (lane >= d) t += y;
        }
        ws[lane] = t - s;
    }
    __syncthreads();
    return x + ws[wid];
}

__global__ void scan2_kernel() {
    __shared__ int s_prefix;
    const int tid = threadIdx.x;
    const int bid = blockIdx.x;
    if (tid < 32) {
        int s = 0;
        if (tid < bid) s += g_bsum[tid];
        int j2 = tid + 32;
        if (j2 < bid) s += g_bsum[j2];
        #pragma unroll
        for (int d = 16; d > 0; d >>= 1) s += __shfl_down_sync(0xffffffffu, s, d);
        if (tid == 0) s_prefix = s;
    }
    __syncthreads();
    const int i = bid * 1024 + tid;
    int v = (i < NN) ? g_deg[i] : 0;
    int inc = block_scan_inc(v, tid);
    if (i < NN) g_rowptr[i] = inc - v + s_prefix;
    if (bid == 0 && tid == 0) g_rowptr[NN] = EE;
}

// -------------------- L5: CSR scatter (col only) ----------------------------
__global__ void scatter_kernel(const int* __restrict__ src,
                               const int* __restrict__ dst) {
    for (int e = blockIdx.x * blockDim.x + threadIdx.x; e < EE;
         e += gridDim.x * blockDim.x) {
        int s = src[e];
        int d = dst[e];
        int pos = g_rowptr[d] + atomicAdd(&g_cursor[d], 1);
        g_col[pos] = s;
    }
}

// -------------------- L6..L21: hop on pre-scaled y (no h RMW) ---------------
__device__ __forceinline__ void acc_y(float4& acc, uint2 r) {
    float2 f01 = __half22float2(*(__half2*)&r.x);
    float2 f23 = __half22float2(*(__half2*)&r.y);
    acc.x += f01.x; acc.y += f01.y;
    acc.z += f23.x; acc.w += f23.y;
}

__global__ void __launch_bounds__(256)
hop_kernel(const uint2* __restrict__ xin, uint2* __restrict__ xout) {
    const int warp = (blockIdx.x * blockDim.x + threadIdx.x) >> 5;
    const int lane = threadIdx.x & 31;
    if (warp >= NN) return;

    uint2 xr = __ldg(&xin[warp * 32 + lane]);
    float4 acc = {0.f, 0.f, 0.f, 0.f};
    acc_y(acc, xr);                          // self term y[d]

    const int start = g_rowptr[warp];
    const int len   = g_deg[warp];

    for (int base = 0; base < len; base += 32) {
        int idx = start + base + lane;
        int c = 0;
        if (base + lane < len) c = __ldg(&g_col[idx]);
        int rem = len - base; if (rem > 32) rem = 32;
        int j = 0;
        for (; j + 8 <= rem; j += 8) {
            int s0 = __shfl_sync(0xffffffffu, c, j + 0);
            int s1 = __shfl_sync(0xffffffffu, c, j + 1);
            int s2 = __shfl_sync(0xffffffffu, c, j + 2);
            int s3 = __shfl_sync(0xffffffffu, c, j + 3);
            int s4 = __shfl_sync(0xffffffffu, c, j + 4);
            int s5 = __shfl_sync(0xffffffffu, c, j + 5);
            int s6 = __shfl_sync(0xffffffffu, c, j + 6);
            int s7 = __shfl_sync(0xffffffffu, c, j + 7);
            uint2 v0 = __ldg(&xin[s0 * 32 + lane]);
            uint2 v1 = __ldg(&xin[s1 * 32 + lane]);
            uint2 v2 = __ldg(&xin[s2 * 32 + lane]);
            uint2 v3 = __ldg(&xin[s3 * 32 + lane]);
            uint2 v4 = __ldg(&xin[s4 * 32 + lane]);
            uint2 v5 = __ldg(&xin[s5 * 32 + lane]);
            uint2 v6 = __ldg(&xin[s6 * 32 + lane]);
            uint2 v7 = __ldg(&xin[s7 * 32 + lane]);
            acc_y(acc, v0);
            acc_y(acc, v1);
            acc_y(acc, v2);
            acc_y(acc, v3);
            acc_y(acc, v4);
            acc_y(acc, v5);
            acc_y(acc, v6);
            acc_y(acc, v7);
        }
        for (; j < rem; j++) {
            int s0 = __shfl_sync(0xffffffffu, c, j);
            uint2 v0 = __ldg(&xin[s0 * 32 + lane]);
            acc_y(acc, v0);
        }
    }

    const float dv = g_dinv[warp];
    const float s2 = dv * dv;                 // y_out = dinv^2 * acc
    __half2 o01 = __floats2half2_rn(s2 * acc.x, s2 * acc.y);
    __half2 o23 = __floats2half2_rn(s2 * acc.z, s2 * acc.w);
    uint2 ow;
    ow.x = *(unsigned int*)&o01;
    ow.y = *(unsigned int*)&o23;
    xout[warp * 32 + lane] = ow;
}

// -------------------- L22: fused h-sum + TF32 tensor-core GEMM --------------
// h[n] = ALPHA*x0[n] + csc[n] * sum_{k=1..K} y_k[n];  out = h @ W^T + bias
#define CHUNK 64
#define SROW  132

__device__ __forceinline__ unsigned f2tf32(float f) {
    unsigned r;
    asm("cvt.rna.tf32.f32 %0, %1;" : "=r"(r) : "f"(f));
    return r;
}

__global__ void __launch_bounds__(256)
gemm_mma_kernel(const float* __restrict__ x0, const float* __restrict__ W,
                const float* __restrict__ bias, float* __restrict__ out) {
    __shared__ float sm[CHUNK * SROW];

    const int tid  = threadIdx.x;
    const int wid  = tid >> 5;
    const int lane = tid & 31;
    const int gq   = lane >> 2;
    const int tg   = lane & 3;

    unsigned a[16][4];
    {
        const int o0 = wid * 16 + gq;
        #pragma unroll
        for (int kt = 0; kt < 16; kt++) {
            int k0 = kt * 8 + tg;
            a[kt][0] = f2tf32(__ldg(&W[o0 * DD + k0]));
            a[kt][1] = f2tf32(__ldg(&W[(o0 + 8) * DD + k0]));
            a[kt][2] = f2tf32(__ldg(&W[o0 * DD + k0 + 4]));
            a[kt][3] = f2tf32(__ldg(&W[(o0 + 8) * DD + k0 + 4]));
        }
    }

    for (int ci = 0; ci < 2; ci++) {
        const int node0 = (blockIdx.x * 2 + ci) * CHUNK;

        // stage h tile on the fly from x0 + 16 y-buffers
        #pragma unroll
        for (int i = 0; i < (CHUNK * 32) / 256; i++) {
            int slot = i * 256 + tid;
            int nl = slot >> 5;
            int g4 = slot & 31;
            int node = node0 + nl;
            float4 acc = {0.f, 0.f, 0.f, 0.f};
            if (node < NN) {
                float4 v0 = __ldg(&((const float4*)x0)[node * 32 + g4]);
                float cs = __ldg(&g_csc[node]);
                float4 ys = {0.f, 0.f, 0.f, 0.f};
                const uint2* p = &g_xbuf[ROW32 + node * 32 + g4];  // y_1
                #pragma unroll
                for (int k = 0; k < KK; k++) {
                    uint2 r = __ldg(p + k * ROW32);
                    acc_y(ys, r);
                }
                acc.x = ALPHA_F * v0.x + cs * ys.x;
                acc.y = ALPHA_F * v0.y + cs * ys.y;
                acc.z = ALPHA_F * v0.z + cs * ys.z;
                acc.w = ALPHA_F * v0.w + cs * ys.w;
            }
            float* pm = &sm[nl * SROW + g4 * 4];
            pm[0] = __uint_as_float(f2tf32(acc.x));
            pm[1] = __uint_as_float(f2tf32(acc.y));
            pm[2] = __uint_as_float(f2tf32(acc.z));
            pm[3] = __uint_as_float(f2tf32(acc.w));
        }
        __syncthreads();

        float c[8][4];
        #pragma unroll
        for (int nt = 0; nt < 8; nt++) {
            c[nt][0] = 0.f; c[nt][1] = 0.f; c[nt][2] = 0.f; c[nt][3] = 0.f;
            #pragma unroll
            for (int kt = 0; kt < 16; kt++) {
                unsigned b0 = __float_as_uint(sm[(nt * 8 + gq) * SROW + kt * 8 + tg]);
                unsigned b1 = __float_as_uint(sm[(nt * 8 + gq) * SROW + kt * 8 + tg + 4]);
                asm("mma.sync.aligned.m16n8k8.row.col.f32.tf32.tf32.f32 "
                    "{%0,%1,%2,%3}, {%4,%5,%6,%7}, {%8,%9}, {%0,%1,%2,%3};"
                    : "+f"(c[nt][0]), "+f"(c[nt][1]), "+f"(c[nt][2]), "+f"(c[nt][3])
                    : "r"(a[kt][0]), "r"(a[kt][1]), "r"(a[kt][2]), "r"(a[kt][3]),
                      "r"(b0), "r"(b1));
            }
        }
        __syncthreads();

        #pragma unroll
        for (int nt = 0; nt < 8; nt++) {
            int nl = nt * 8 + 2 * tg;
            int ol = wid * 16 + gq;
            sm[nl * SROW + ol]             = c[nt][0];
            sm[(nl + 1) * SROW + ol]       = c[nt][1];
            sm[nl * SROW + ol + 8]         = c[nt][2];
            sm[(nl + 1) * SROW + ol + 8]   = c[nt][3];
        }
        __syncthreads();

        #pragma unroll
        for (int i = 0; i < (CHUNK * 32) / 256; i++) {
            int slot = i * 256 + tid;
            int nl = slot >> 5;
            int o4 = slot & 31;
            int node = node0 + nl;
            if (node < NN) {
                float4 bv = __ldg(&((const float4*)bias)[o4]);
                float* p = &sm[nl * SROW + o4 * 4];
                float4 r;
                r.x = p[0] + bv.x; r.y = p[1] + bv.y;
                r.z = p[2] + bv.z; r.w = p[3] + bv.w;
                ((float4*)out)[node * 32 + o4] = r;
            }
        }
        __syncthreads();
    }
}

// -------------------- L23: reset deg for next graph replay -------------------
__global__ void reset_kernel() {
    int v = blockIdx.x * blockDim.x + threadIdx.x;
    if (v < NN) g_deg[v] = 0;
}

// -------------------- launch -------------------------------------------------
extern "C" void kernel_launch(void* const* d_in, const int* in_sizes, int n_in,
                              void* d_out, int out_size) {
    const float* x0   = (const float*)d_in[0];
    const int*   ei   = (const int*)  d_in[1];
    const float* W    = (const float*)d_in[2];
    const float* bias = (const float*)d_in[3];
    const int* src = ei;
    const int* dst = ei + EE;
    float* out = (float*)d_out;

    void* pX;
    cudaGetSymbolAddress(&pX, g_xbuf);
    uint2* xb = (uint2*)pX;

    count_deg_kernel<<<2048, 256>>>(dst);                     // L1
    prep_kernel<<<(NN * 32 + 255) / 256, 256>>>(x0);          // L2
    scan1_kernel<<<NBLK, 1024>>>();                           // L3
    scan2_kernel<<<NBLK, 1024>>>();                           // L4
    scatter_kernel<<<2048, 256>>>(src, dst);                  // L5

    for (int k = 0; k < KK; k++) {                            // L6..L21
        hop_kernel<<<(NN + 7) / 8, 256>>>(xb + k * ROW32, xb + (k + 1) * ROW32);
    }

    gemm_mma_kernel<<<NPAD / (2 * CHUNK), 256>>>(x0, W, bias, out);  // L22
    reset_kernel<<<(NN + 1023) / 1024, 1024>>>();                    // L23
}

// round 15
// speedup vs baseline: 1.0586x; 1.0586x over previous
#include <cuda_runtime.h>
#include <cuda_fp16.h>

#define NN   50000
#define EE   1600000
#define DD   128
#define KK   16
#define ALPHA_F 0.05f
#define CW_F    (0.95f / 16.0f)
#define NPAD 50048
#define NBLK 49            // ceil(NN/1024)
#define ROW32 (NPAD * 32)  // uint2 groups per buffer

// -------------------- scratch (static device globals; no allocs) ------------
__device__ uint2 g_ybuf[4 * ROW32];     // 4 rotating fp16 y buffers (~51 MB)
__device__ float g_h [NPAD * DD];       // fp32 h accumulator
__device__ int   g_deg[NN];             // edge in-degree (no self loop); 0 at entry
__device__ float g_dinv[NN];            // 1/sqrt(deg+1)
__device__ float g_csc[NN];             // CW_F * sqrt(deg+1)
__device__ int   g_rowptr[NN + 1];
__device__ int   g_cursor[NN];
__device__ int   g_col[EE];
__device__ int   g_bsum[NBLK];

// -------------------- L1: degree count (deg starts at 0) --------------------
__global__ void count_deg_kernel(const int* __restrict__ dst) {
    for (int e = blockIdx.x * blockDim.x + threadIdx.x; e < EE;
         e += gridDim.x * blockDim.x) {
        atomicAdd(&g_deg[dst[e]], 1);
    }
}

// -------------------- L2: cursor + dinv + csc + fp16 y0 + h init ------------
__global__ void prep_kernel(const float* __restrict__ x0) {
    int idx = blockIdx.x * blockDim.x + threadIdx.x;
    const int total = NN * 32;
    if (idx < total) {
        int node = idx >> 5;
        float dv = rsqrtf((float)(g_deg[node] + 1));
        float4 v = ((const float4*)x0)[idx];
        __half2 p01 = __floats2half2_rn(dv * v.x, dv * v.y);
        __half2 p23 = __floats2half2_rn(dv * v.z, dv * v.w);
        uint2 o;
        o.x = *(unsigned int*)&p01;
        o.y = *(unsigned int*)&p23;
        g_ybuf[idx] = o;                                   // buffer 0 = y_0
        float4 hv;
        hv.x = ALPHA_F * v.x; hv.y = ALPHA_F * v.y;
        hv.z = ALPHA_F * v.z; hv.w = ALPHA_F * v.w;
        ((float4*)g_h)[idx] = hv;
    }
    if (idx < NN) {
        float dp1 = (float)(g_deg[idx] + 1);
        g_dinv[idx] = rsqrtf(dp1);
        g_csc[idx]  = CW_F * sqrtf(dp1);
        g_cursor[idx] = 0;
    }
}

// -------------------- L3/L4: scan --------------------------------------------
__global__ void scan1_kernel() {
    __shared__ int ws[32];
    int tid = threadIdx.x;
    int i = blockIdx.x * 1024 + tid;
    int v = (i < NN) ? g_deg[i] : 0;
    #pragma unroll
    for (int d = 16; d > 0; d >>= 1) v += __shfl_down_sync(0xffffffffu, v, d);
    if ((tid & 31) == 0) ws[tid >> 5] = v;
    __syncthreads();
    if (tid < 32) {
        int s = ws[tid];
        #pragma unroll
        for (int d = 16; d > 0; d >>= 1) s += __shfl_down_sync(0xffffffffu, s, d);
        if (tid == 0) g_bsum[blockIdx.x] = s;
    }
}

__device__ __forceinline__ int block_scan_inc(int v, int tid) {
    __shared__ int ws[32];
    const int lane = tid & 31, wid = tid >> 5;
    int x = v;
    #pragma unroll
    for (int d = 1; d < 32; d <<= 1) {
        int y = __shfl_up_sync(0xffffffffu, x, d);
        if (lane >= d) x += y;
    }
    if (lane == 31) ws[wid] = x;
    __syncthreads();
    if (wid == 0) {
        int s = ws[lane];
        int t = s;
        #pragma unroll
        for (int d = 1; d < 32; d <<= 1) {
            int y = __shfl_up_sync(0xffffffffu, t, d);
            if (lane >= d) t += y;
        }
        ws[lane] = t - s;
    }
    __syncthreads();
    return x + ws[wid];
}

__global__ void scan2_kernel() {
    __shared__ int s_prefix;
    const int tid = threadIdx.x;
    const int bid = blockIdx.x;
    if (tid < 32) {
        int s = 0;
        if (tid < bid) s += g_bsum[tid];
        int j2 = tid + 32;
        if (j2 < bid) s += g_bsum[j2];
        #pragma unroll
        for (int d = 16; d > 0; d >>= 1) s += __shfl_down_sync(0xffffffffu, s, d);
        if (tid == 0) s_prefix = s;
    }
    __syncthreads();
    const int i = bid * 1024 + tid;
    int v = (i < NN) ? g_deg[i] : 0;
    int inc = block_scan_inc(v, tid);
    if (i < NN) g_rowptr[i] = inc - v + s_prefix;
    if (bid == 0 && tid == 0) g_rowptr[NN] = EE;
}

// -------------------- L5: CSR scatter (col only) ----------------------------
__global__ void scatter_kernel(const int* __restrict__ src,
                               const int* __restrict__ dst) {
    for (int e = blockIdx.x * blockDim.x + threadIdx.x; e < EE;
         e += gridDim.x * blockDim.x) {
        int s = src[e];
        int d = dst[e];
        int pos = g_rowptr[d] + atomicAdd(&g_cursor[d], 1);
        g_col[pos] = s;
    }
}

// -------------------- hop core -----------------------------------------------
__device__ __forceinline__ void acc_y(float4& acc, uint2 r) {
    float2 f01 = __half22float2(*(__half2*)&r.x);
    float2 f23 = __half22float2(*(__half2*)&r.y);
    acc.x += f01.x; acc.y += f01.y;
    acc.z += f23.x; acc.w += f23.y;
}

__device__ __forceinline__ float4 gather_row(const uint2* __restrict__ xin,
                                             int start, int len, int lane,
                                             uint2 xr) {
    float4 acc = {0.f, 0.f, 0.f, 0.f};
    acc_y(acc, xr);                          // self term y[d]
    for (int base = 0; base < len; base += 32) {
        int idx = start + base + lane;
        int c = 0;
        if (base + lane < len) c = __ldg(&g_col[idx]);
        int rem = len - base; if (rem > 32) rem = 32;
        int j = 0;
        for (; j + 8 <= rem; j += 8) {
            int s0 = __shfl_sync(0xffffffffu, c, j + 0);
            int s1 = __shfl_sync(0xffffffffu, c, j + 1);
            int s2 = __shfl_sync(0xffffffffu, c, j + 2);
            int s3 = __shfl_sync(0xffffffffu, c, j + 3);
            int s4 = __shfl_sync(0xffffffffu, c, j + 4);
            int s5 = __shfl_sync(0xffffffffu, c, j + 5);
            int s6 = __shfl_sync(0xffffffffu, c, j + 6);
            int s7 = __shfl_sync(0xffffffffu, c, j + 7);
            uint2 v0 = __ldg(&xin[s0 * 32 + lane]);
            uint2 v1 = __ldg(&xin[s1 * 32 + lane]);
            uint2 v2 = __ldg(&xin[s2 * 32 + lane]);
            uint2 v3 = __ldg(&xin[s3 * 32 + lane]);
            uint2 v4 = __ldg(&xin[s4 * 32 + lane]);
            uint2 v5 = __ldg(&xin[s5 * 32 + lane]);
            uint2 v6 = __ldg(&xin[s6 * 32 + lane]);
            uint2 v7 = __ldg(&xin[s7 * 32 + lane]);
            acc_y(acc, v0);
            acc_y(acc, v1);
            acc_y(acc, v2);
            acc_y(acc, v3);
            acc_y(acc, v4);
            acc_y(acc, v5);
            acc_y(acc, v6);
            acc_y(acc, v7);
        }
        for (; j < rem; j++) {
            int s0 = __shfl_sync(0xffffffffu, c, j);
            uint2 v0 = __ldg(&xin[s0 * 32 + lane]);
            acc_y(acc, v0);
        }
    }
    return acc;
}

// plain hop: y_out only (hops k with k % 4 != 0)
__global__ void __launch_bounds__(256)
hop_kernel(const uint2* __restrict__ xin, uint2* __restrict__ xout) {
    const int warp = (blockIdx.x * blockDim.x + threadIdx.x) >> 5;
    const int lane = threadIdx.x & 31;
    if (warp >= NN) return;

    uint2 xr = __ldg(&xin[warp * 32 + lane]);
    float4 acc = gather_row(xin, g_rowptr[warp], g_deg[warp], lane, xr);

    const float dv = g_dinv[warp];
    const float s2 = dv * dv;
    __half2 o01 = __floats2half2_rn(s2 * acc.x, s2 * acc.y);
    __half2 o23 = __floats2half2_rn(s2 * acc.z, s2 * acc.w);
    uint2 ow;
    ow.x = *(unsigned int*)&o01;
    ow.y = *(unsigned int*)&o23;
    xout[warp * 32 + lane] = ow;
}

// group hop (k % 4 == 0): y_out + h update for the whole 4-hop group
// h += csc*(y_{k-3} + y_{k-2} + y_{k-1}) + CW*dinv*acc
__global__ void __launch_bounds__(256)
hop4_kernel(const uint2* __restrict__ xin, uint2* __restrict__ xout,
            const uint2* __restrict__ ya, const uint2* __restrict__ yb,
            float* __restrict__ h) {
    const int warp = (blockIdx.x * blockDim.x + threadIdx.x) >> 5;
    const int lane = threadIdx.x & 31;
    if (warp >= NN) return;

    uint2 xr = __ldg(&xin[warp * 32 + lane]);    // y_{k-1}
    float4 acc = gather_row(xin, g_rowptr[warp], g_deg[warp], lane, xr);

    const float dv = g_dinv[warp];
    const float s2 = dv * dv;
    __half2 o01 = __floats2half2_rn(s2 * acc.x, s2 * acc.y);
    __half2 o23 = __floats2half2_rn(s2 * acc.z, s2 * acc.w);
    uint2 ow;
    ow.x = *(unsigned int*)&o01;
    ow.y = *(unsigned int*)&o23;
    xout[warp * 32 + lane] = ow;

    // group h update
    float4 ysum = {0.f, 0.f, 0.f, 0.f};
    acc_y(ysum, xr);                              // y_{k-1}
    acc_y(ysum, __ldg(&ya[warp * 32 + lane]));    // y_{k-3}
    acc_y(ysum, __ldg(&yb[warp * 32 + lane]));    // y_{k-2}

    const float cs = g_csc[warp];                 // CW / dinv
    const float cw = CW_F * dv;                   // CW * dinv (for own acc)
    float4 hv = ((float4*)h)[warp * 32 + lane];
    hv.x += cs * ysum.x + cw * acc.x;
    hv.y += cs * ysum.y + cw * acc.y;
    hv.z += cs * ysum.z + cw * acc.z;
    hv.w += cs * ysum.w + cw * acc.w;
    ((float4*)h)[warp * 32 + lane] = hv;
}

// -------------------- L22: TF32 tensor-core GEMM on g_h ---------------------
#define CHUNK 64
#define SROW  132

__device__ __forceinline__ unsigned f2tf32(float f) {
    unsigned r;
    asm("cvt.rna.tf32.f32 %0, %1;" : "=r"(r) : "f"(f));
    return r;
}

__global__ void __launch_bounds__(256)
gemm_mma_kernel(const float* __restrict__ h, const float* __restrict__ W,
                const float* __restrict__ bias, float* __restrict__ out) {
    __shared__ float sm[CHUNK * SROW];

    const int tid  = threadIdx.x;
    const int wid  = tid >> 5;
    const int lane = tid & 31;
    const int gq   = lane >> 2;
    const int tg   = lane & 3;

    unsigned a[16][4];
    {
        const int o0 = wid * 16 + gq;
        #pragma unroll
        for (int kt = 0; kt < 16; kt++) {
            int k0 = kt * 8 + tg;
            a[kt][0] = f2tf32(__ldg(&W[o0 * DD + k0]));
            a[kt][1] = f2tf32(__ldg(&W[(o0 + 8) * DD + k0]));
            a[kt][2] = f2tf32(__ldg(&W[o0 * DD + k0 + 4]));
            a[kt][3] = f2tf32(__ldg(&W[(o0 + 8) * DD + k0 + 4]));
        }
    }

    for (int ci = 0; ci < 2; ci++) {
        const int node0 = (blockIdx.x * 2 + ci) * CHUNK;

        #pragma unroll
        for (int i = 0; i < (CHUNK * 32) / 256; i++) {
            int slot = i * 256 + tid;
            int nl = slot >> 5;
            int g4 = slot & 31;
            float4 v = __ldg(&((const float4*)h)[(node0 + nl) * 32 + g4]);
            float* p = &sm[nl * SROW + g4 * 4];
            p[0] = __uint_as_float(f2tf32(v.x));
            p[1] = __uint_as_float(f2tf32(v.y));
            p[2] = __uint_as_float(f2tf32(v.z));
            p[3] = __uint_as_float(f2tf32(v.w));
        }
        __syncthreads();

        float c[8][4];
        #pragma unroll
        for (int nt = 0; nt < 8; nt++) {
            c[nt][0] = 0.f; c[nt][1] = 0.f; c[nt][2] = 0.f; c[nt][3] = 0.f;
            #pragma unroll
            for (int kt = 0; kt < 16; kt++) {
                unsigned b0 = __float_as_uint(sm[(nt * 8 + gq) * SROW + kt * 8 + tg]);
                unsigned b1 = __float_as_uint(sm[(nt * 8 + gq) * SROW + kt * 8 + tg + 4]);
                asm("mma.sync.aligned.m16n8k8.row.col.f32.tf32.tf32.f32 "
                    "{%0,%1,%2,%3}, {%4,%5,%6,%7}, {%8,%9}, {%0,%1,%2,%3};"
                    : "+f"(c[nt][0]), "+f"(c[nt][1]), "+f"(c[nt][2]), "+f"(c[nt][3])
                    : "r"(a[kt][0]), "r"(a[kt][1]), "r"(a[kt][2]), "r"(a[kt][3]),
                      "r"(b0), "r"(b1));
            }
        }
        __syncthreads();

        #pragma unroll
        for (int nt = 0; nt < 8; nt++) {
            int nl = nt * 8 + 2 * tg;
            int ol = wid * 16 + gq;
            sm[nl * SROW + ol]             = c[nt][0];
            sm[(nl + 1) * SROW + ol]       = c[nt][1];
            sm[nl * SROW + ol + 8]         = c[nt][2];
            sm[(nl + 1) * SROW + ol + 8]   = c[nt][3];
        }
        __syncthreads();

        #pragma unroll
        for (int i = 0; i < (CHUNK * 32) / 256; i++) {
            int slot = i * 256 + tid;
            int nl = slot >> 5;
            int o4 = slot & 31;
            int node = node0 + nl;
            if (node < NN) {
                float4 bv = __ldg(&((const float4*)bias)[o4]);
                float* p = &sm[nl * SROW + o4 * 4];
                float4 r;
                r.x = p[0] + bv.x; r.y = p[1] + bv.y;
                r.z = p[2] + bv.z; r.w = p[3] + bv.w;
                ((float4*)out)[node * 32 + o4] = r;
            }
        }
        __syncthreads();
    }
}

// -------------------- L23: reset deg for next graph replay -------------------
__global__ void reset_kernel() {
    int v = blockIdx.x * blockDim.x + threadIdx.x;
    if (v < NN) g_deg[v] = 0;
}

// -------------------- launch -------------------------------------------------
extern "C" void kernel_launch(void* const* d_in, const int* in_sizes, int n_in,
                              void* d_out, int out_size) {
    const float* x0   = (const float*)d_in[0];
    const int*   ei   = (const int*)  d_in[1];
    const float* W    = (const float*)d_in[2];
    const float* bias = (const float*)d_in[3];
    const int* src = ei;
    const int* dst = ei + EE;
    float* out = (float*)d_out;

    void *pY, *ph;
    cudaGetSymbolAddress(&pY, g_ybuf);
    cudaGetSymbolAddress(&ph, g_h);
    uint2* yb = (uint2*)pY;
    float* h  = (float*)ph;

    count_deg_kernel<<<2048, 256>>>(dst);                     // L1
    prep_kernel<<<(NN * 32 + 255) / 256, 256>>>(x0);          // L2 (y_0 -> buf0)
    scan1_kernel<<<NBLK, 1024>>>();                           // L3
    scan2_kernel<<<NBLK, 1024>>>();                           // L4
    scatter_kernel<<<2048, 256>>>(src, dst);                  // L5

    const int grid = (NN + 7) / 8;
    for (int k = 1; k <= KK; k++) {                           // L6..L21
        uint2* xin  = yb + ((k - 1) & 3) * ROW32;
        uint2* xout = yb + (k & 3) * ROW32;
        if ((k & 3) == 0) {
            uint2* ya = yb + ((k - 3) & 3) * ROW32;   // y_{k-3}
            uint2* ybp = yb + ((k - 2) & 3) * ROW32;  // y_{k-2}
            hop4_kernel<<<grid, 256>>>(xin, xout, ya, ybp, h);
        } else {
            hop_kernel<<<grid, 256>>>(xin, xout);
        }
    }

    gemm_mma_kernel<<<NPAD / (2 * CHUNK), 256>>>(h, W, bias, out);  // L22
    reset_kernel<<<(NN + 1023) / 1024, 1024>>>();                   // L23
}